// round 15
// baseline (speedup 1.0000x reference)
#include <cuda_runtime.h>
#include <cuda_fp16.h>

#define N_ITEMS 100000
#define KNN_K   5
#define VEC     32                 // 32 float4 (or uint2) per 128-elem row
#define WARPS_PER_BLOCK 8
#define THREADS (WARPS_PER_BLOCK * 32)
#define PAIRS   (N_ITEMS / 2)      // 50000 row-pairs
#define CHUNK   2                  // pairs per warp-steal (25k atomics/phase)

// Layer-1 output in fp16 (25.6 MB). x0 (51.2) + x1h (25.6) = 77 MB stays
// L2-resident across the phase boundary; out is write-through (no L2 alloc).
__device__ uint2 g_x1h[(size_t)N_ITEMS * VEC];
// Monotonic grid-barrier ticket (each launch consumes exactly gridDim.x).
__device__ unsigned g_ticket;
// Per-warp work-steal counters. g_ctr2 reset by block 0 BEFORE the barrier
// (ordered for phase 2 by the barrier); g_ctr1 reset AFTER the barrier
// (ordered for the next launch by stream order). Zero-init covers launch 1.
__device__ unsigned g_ctr1;
__device__ unsigned g_ctr2;

__device__ __forceinline__ void grid_barrier() {
    __syncthreads();
    if (threadIdx.x == 0) {
        __threadfence();                                    // release phase-1 stores
        unsigned t = atomicAdd(&g_ticket, 1u);
        unsigned target = (t / gridDim.x + 1u) * gridDim.x;
        while (*(volatile unsigned*)&g_ticket < target) __nanosleep(64);
        __threadfence();                                    // acquire
    }
    __syncthreads();
}

// ---- phase bodies (R6-verified load batching) -------------------------------

__device__ __forceinline__ void do_pair_phase1(
    const float4* __restrict__ x0, const int* __restrict__ idx,
    int lane, int row0, float c)
{
    int my = 0;
    if (lane < 2 * KNN_K) my = __ldg(idx + row0 * KNN_K + lane);
    int j0 = __shfl_sync(0xffffffffu, my, 0);
    int j1 = __shfl_sync(0xffffffffu, my, 1);
    int j2 = __shfl_sync(0xffffffffu, my, 2);
    int j3 = __shfl_sync(0xffffffffu, my, 3);
    int j4 = __shfl_sync(0xffffffffu, my, 4);
    int j5 = __shfl_sync(0xffffffffu, my, 5);
    int j6 = __shfl_sync(0xffffffffu, my, 6);
    int j7 = __shfl_sync(0xffffffffu, my, 7);
    int j8 = __shfl_sync(0xffffffffu, my, 8);
    int j9 = __shfl_sync(0xffffffffu, my, 9);

    float4 a0 = __ldg(x0 + (size_t)j0 * VEC + lane);
    float4 a1 = __ldg(x0 + (size_t)j1 * VEC + lane);
    float4 a2 = __ldg(x0 + (size_t)j2 * VEC + lane);
    float4 a3 = __ldg(x0 + (size_t)j3 * VEC + lane);
    float4 a4 = __ldg(x0 + (size_t)j4 * VEC + lane);
    float4 b0 = __ldg(x0 + (size_t)j5 * VEC + lane);
    float4 b1 = __ldg(x0 + (size_t)j6 * VEC + lane);
    float4 b2 = __ldg(x0 + (size_t)j7 * VEC + lane);
    float4 b3 = __ldg(x0 + (size_t)j8 * VEC + lane);
    float4 b4 = __ldg(x0 + (size_t)j9 * VEC + lane);

    float4 s0, s1;
    s0.x = c * (a0.x + a1.x + a2.x + a3.x + a4.x);
    s0.y = c * (a0.y + a1.y + a2.y + a3.y + a4.y);
    s0.z = c * (a0.z + a1.z + a2.z + a3.z + a4.z);
    s0.w = c * (a0.w + a1.w + a2.w + a3.w + a4.w);
    s1.x = c * (b0.x + b1.x + b2.x + b3.x + b4.x);
    s1.y = c * (b0.y + b1.y + b2.y + b3.y + b4.y);
    s1.z = c * (b0.z + b1.z + b2.z + b3.z + b4.z);
    s1.w = c * (b0.w + b1.w + b2.w + b3.w + b4.w);

    __half2 h00 = __floats2half2_rn(s0.x, s0.y);
    __half2 h01 = __floats2half2_rn(s0.z, s0.w);
    __half2 h10 = __floats2half2_rn(s1.x, s1.y);
    __half2 h11 = __floats2half2_rn(s1.z, s1.w);
    uint2 u0, u1;
    u0.x = *reinterpret_cast<unsigned int*>(&h00);
    u0.y = *reinterpret_cast<unsigned int*>(&h01);
    u1.x = *reinterpret_cast<unsigned int*>(&h10);
    u1.y = *reinterpret_cast<unsigned int*>(&h11);
    g_x1h[(size_t)row0 * VEC + lane] = u0;
    g_x1h[(size_t)(row0 + 1) * VEC + lane] = u1;
}

__device__ __forceinline__ void do_pair_phase2(
    const float4* __restrict__ x0, const int* __restrict__ idx,
    float4* __restrict__ out, int lane, int row0, float c)
{
    int my = 0;
    if (lane < 2 * KNN_K) my = __ldg(idx + row0 * KNN_K + lane);
    int j0 = __shfl_sync(0xffffffffu, my, 0);
    int j1 = __shfl_sync(0xffffffffu, my, 1);
    int j2 = __shfl_sync(0xffffffffu, my, 2);
    int j3 = __shfl_sync(0xffffffffu, my, 3);
    int j4 = __shfl_sync(0xffffffffu, my, 4);
    int j5 = __shfl_sync(0xffffffffu, my, 5);
    int j6 = __shfl_sync(0xffffffffu, my, 6);
    int j7 = __shfl_sync(0xffffffffu, my, 7);
    int j8 = __shfl_sync(0xffffffffu, my, 8);
    int j9 = __shfl_sync(0xffffffffu, my, 9);

    const uint2* x1h = g_x1h;
    uint2 g0 = __ldg(x1h + (size_t)j0 * VEC + lane);   // L2-warm (phase 1)
    uint2 g1 = __ldg(x1h + (size_t)j1 * VEC + lane);
    uint2 g2 = __ldg(x1h + (size_t)j2 * VEC + lane);
    uint2 g3 = __ldg(x1h + (size_t)j3 * VEC + lane);
    uint2 g4 = __ldg(x1h + (size_t)j4 * VEC + lane);
    uint2 h0 = __ldg(x1h + (size_t)j5 * VEC + lane);
    uint2 h1 = __ldg(x1h + (size_t)j6 * VEC + lane);
    uint2 h2 = __ldg(x1h + (size_t)j7 * VEC + lane);
    uint2 h3 = __ldg(x1h + (size_t)j8 * VEC + lane);
    uint2 h4 = __ldg(x1h + (size_t)j9 * VEC + lane);
    uint2 gr0 = __ldg(x1h + (size_t)row0 * VEC + lane);
    uint2 gr1 = __ldg(x1h + (size_t)(row0 + 1) * VEC + lane);
    float4 r00 = __ldg(x0 + (size_t)row0 * VEC + lane);       // L2-warm
    float4 r01 = __ldg(x0 + (size_t)(row0 + 1) * VEC + lane);

    float2 A0 = __half22float2(*reinterpret_cast<__half2*>(&g0.x));
    float2 A1 = __half22float2(*reinterpret_cast<__half2*>(&g0.y));
    float2 B0 = __half22float2(*reinterpret_cast<__half2*>(&g1.x));
    float2 B1 = __half22float2(*reinterpret_cast<__half2*>(&g1.y));
    float2 C0 = __half22float2(*reinterpret_cast<__half2*>(&g2.x));
    float2 C1 = __half22float2(*reinterpret_cast<__half2*>(&g2.y));
    float2 D0 = __half22float2(*reinterpret_cast<__half2*>(&g3.x));
    float2 D1 = __half22float2(*reinterpret_cast<__half2*>(&g3.y));
    float2 E0 = __half22float2(*reinterpret_cast<__half2*>(&g4.x));
    float2 E1 = __half22float2(*reinterpret_cast<__half2*>(&g4.y));
    float2 R0 = __half22float2(*reinterpret_cast<__half2*>(&gr0.x));
    float2 R1 = __half22float2(*reinterpret_cast<__half2*>(&gr0.y));

    float4 s0;
    s0.x = r00.x + R0.x + c * (A0.x + B0.x + C0.x + D0.x + E0.x);
    s0.y = r00.y + R0.y + c * (A0.y + B0.y + C0.y + D0.y + E0.y);
    s0.z = r00.z + R1.x + c * (A1.x + B1.x + C1.x + D1.x + E1.x);
    s0.w = r00.w + R1.y + c * (A1.y + B1.y + C1.y + D1.y + E1.y);
    __stwt(out + (size_t)row0 * VEC + lane, s0);   // write-through: no L2 alloc

    A0 = __half22float2(*reinterpret_cast<__half2*>(&h0.x));
    A1 = __half22float2(*reinterpret_cast<__half2*>(&h0.y));
    B0 = __half22float2(*reinterpret_cast<__half2*>(&h1.x));
    B1 = __half22float2(*reinterpret_cast<__half2*>(&h1.y));
    C0 = __half22float2(*reinterpret_cast<__half2*>(&h2.x));
    C1 = __half22float2(*reinterpret_cast<__half2*>(&h2.y));
    D0 = __half22float2(*reinterpret_cast<__half2*>(&h3.x));
    D1 = __half22float2(*reinterpret_cast<__half2*>(&h3.y));
    E0 = __half22float2(*reinterpret_cast<__half2*>(&h4.x));
    E1 = __half22float2(*reinterpret_cast<__half2*>(&h4.y));
    R0 = __half22float2(*reinterpret_cast<__half2*>(&gr1.x));
    R1 = __half22float2(*reinterpret_cast<__half2*>(&gr1.y));

    float4 s1;
    s1.x = r01.x + R0.x + c * (A0.x + B0.x + C0.x + D0.x + E0.x);
    s1.y = r01.y + R0.y + c * (A0.y + B0.y + C0.y + D0.y + E0.y);
    s1.z = r01.z + R1.x + c * (A1.x + B1.x + C1.x + D1.x + E1.x);
    s1.w = r01.w + R1.y + c * (A1.y + B1.y + C1.y + D1.y + E1.y);
    __stwt(out + (size_t)(row0 + 1) * VEC + lane, s1);
}

// Fused GCN with PER-WARP work stealing: no __syncthreads in the steal loops,
// so warps stream independently (R14's block-level steal lockstepped all 8
// warps to the slowest gather chain each chunk -> 49.9us). (256,4) gives a
// 64-reg budget so the 10-gather batches really coexist.
__global__ __launch_bounds__(THREADS, 4) void gcn_fused(
    const float4* __restrict__ x0,
    const int*    __restrict__ idx,
    float4*       __restrict__ out,
    float c)
{
    int lane = threadIdx.x & 31;

    if (blockIdx.x == 0 && threadIdx.x == 0) g_ctr2 = 0;  // for THIS launch's phase 2

    // ---------------- phase 1: x1 = c * A x0 (per-warp steal) ----------------
    for (;;) {
        unsigned base = 0;
        if (lane == 0) base = atomicAdd(&g_ctr1, (unsigned)CHUNK);
        base = __shfl_sync(0xffffffffu, base, 0);
        if (base >= PAIRS) break;
        #pragma unroll
        for (int p = 0; p < CHUNK; p++) {
            unsigned pair = base + p;
            if (pair < PAIRS)
                do_pair_phase1(x0, idx, lane, (int)pair * 2, c);
        }
    }

    grid_barrier();

    if (blockIdx.x == 0 && threadIdx.x == 0) g_ctr1 = 0;  // for the NEXT launch

    // -------- phase 2: out = x0 + x1 + c * A x1 (per-warp steal) --------
    for (;;) {
        unsigned base = 0;
        if (lane == 0) base = atomicAdd(&g_ctr2, (unsigned)CHUNK);
        base = __shfl_sync(0xffffffffu, base, 0);
        if (base >= PAIRS) break;
        #pragma unroll
        for (int p = 0; p < CHUNK; p++) {
            unsigned pair = base + p;
            if (pair < PAIRS)
                do_pair_phase2(x0, idx, out, lane, (int)pair * 2, c);
        }
    }
}

// ---------------- fallback (R6 two-kernel path) -----------------------------
#define FB_BLOCKS (PAIRS / WARPS_PER_BLOCK)

__global__ __launch_bounds__(THREADS) void spmm_layer1(
    const float4* __restrict__ x0, const int* __restrict__ idx, float c)
{
    int warp = blockIdx.x * WARPS_PER_BLOCK + (threadIdx.x >> 5);
    int lane = threadIdx.x & 31;
    do_pair_phase1(x0, idx, lane, warp * 2, c);
}

__global__ __launch_bounds__(THREADS) void spmm_layer2(
    const float4* __restrict__ x0, const int* __restrict__ idx,
    float4* __restrict__ out, float c)
{
    int warp = blockIdx.x * WARPS_PER_BLOCK + (threadIdx.x >> 5);
    int lane = threadIdx.x & 31;
    do_pair_phase2(x0, idx, out, lane, warp * 2, c);
}
// ---------------------------------------------------------------------------

extern "C" void kernel_launch(void* const* d_in, const int* in_sizes, int n_in,
                              void* d_out, int out_size)
{
    const float4* x0  = (const float4*)d_in[0];   // item_rep [N, 128] f32
    const int*    idx = (const int*)d_in[1];      // knn_ind  [N, 5] i32
    float4*       out = (float4*)d_out;

    // vals[n,k] = (K+1e-7)^-0.5 * (K+1e-7)^-0.5 == 1/(K+1e-7): a constant.
    float c = (float)(1.0 / (5.0 + 1e-7));

    int dev = 0, sms = 0;
    cudaGetDevice(&dev);
    cudaDeviceGetAttribute(&sms, cudaDevAttrMultiProcessorCount, dev);

    if (sms > 0) {
        int grid = sms * 4;   // co-resident under __launch_bounds__(256, 4)
        gcn_fused<<<grid, THREADS>>>(x0, idx, out, c);
    } else {
        spmm_layer1<<<FB_BLOCKS, THREADS>>>(x0, idx, c);
        spmm_layer2<<<FB_BLOCKS, THREADS>>>(x0, idx, out, c);
    }
}

// round 16
// speedup vs baseline: 1.6304x; 1.6304x over previous
#include <cuda_runtime.h>
#include <cuda_fp16.h>

#define N_ITEMS 100000
#define KNN_K   5
#define VEC     32                 // 32 float4 (or uint2) per 128-elem row
#define WARPS_PER_BLOCK 8
#define THREADS (WARPS_PER_BLOCK * 32)
// 2 rows per warp, no tail: 100000 / 2 = 50000 warps = 6250 blocks exactly.
#define BLOCKS  (N_ITEMS / 2 / WARPS_PER_BLOCK)

// Intermediate layer-1 output in fp16 (25.6 MB): halves layer2's gather bytes
// and keeps the hot read set (x0 51.2 + x1h 25.6 = 77 MB) inside the 126 MB L2.
__device__ uint2 g_x1h[(size_t)N_ITEMS * VEC];

// ---- L2 evict_last policy (R10-verified: only layer2 config < 23.4 us) -----
__device__ __forceinline__ unsigned long long mk_evict_last_policy() {
    unsigned long long p;
    asm("createpolicy.fractional.L2::evict_last.b64 %0, 1.0;" : "=l"(p));
    return p;
}
__device__ __forceinline__ uint2 ldg_keep_u2(const uint2* p, unsigned long long pol) {
    uint2 v;
    asm("ld.global.nc.L2::cache_hint.v2.u32 {%0,%1}, [%2], %3;"
        : "=r"(v.x), "=r"(v.y) : "l"(p), "l"(pol));
    return v;
}
// ---------------------------------------------------------------------------

// Kernel 1: x1h[n] = fp16( c * sum_k x0[idx[n,k]] ), 2 rows/warp.
// EXACT R6 body (15.9 us measured) — no policy machinery (R10 showed the
// createpolicy/stg-hint overhead cost layer1 ~4 us).
__global__ __launch_bounds__(THREADS) void spmm_layer1(
    const float4* __restrict__ x0,
    const int*    __restrict__ idx,
    float c)
{
    int warp = blockIdx.x * WARPS_PER_BLOCK + (threadIdx.x >> 5);
    int lane = threadIdx.x & 31;
    int row0 = warp * 2;

    // One lane-parallel load covers both rows' 10 indices; shfl distributes.
    int my = 0;
    if (lane < 2 * KNN_K) my = __ldg(idx + row0 * KNN_K + lane);
    int j0 = __shfl_sync(0xffffffffu, my, 0);
    int j1 = __shfl_sync(0xffffffffu, my, 1);
    int j2 = __shfl_sync(0xffffffffu, my, 2);
    int j3 = __shfl_sync(0xffffffffu, my, 3);
    int j4 = __shfl_sync(0xffffffffu, my, 4);
    int j5 = __shfl_sync(0xffffffffu, my, 5);
    int j6 = __shfl_sync(0xffffffffu, my, 6);
    int j7 = __shfl_sync(0xffffffffu, my, 7);
    int j8 = __shfl_sync(0xffffffffu, my, 8);
    int j9 = __shfl_sync(0xffffffffu, my, 9);

    float4 a0 = __ldg(x0 + (size_t)j0 * VEC + lane);
    float4 a1 = __ldg(x0 + (size_t)j1 * VEC + lane);
    float4 a2 = __ldg(x0 + (size_t)j2 * VEC + lane);
    float4 a3 = __ldg(x0 + (size_t)j3 * VEC + lane);
    float4 a4 = __ldg(x0 + (size_t)j4 * VEC + lane);
    float4 b0 = __ldg(x0 + (size_t)j5 * VEC + lane);
    float4 b1 = __ldg(x0 + (size_t)j6 * VEC + lane);
    float4 b2 = __ldg(x0 + (size_t)j7 * VEC + lane);
    float4 b3 = __ldg(x0 + (size_t)j8 * VEC + lane);
    float4 b4 = __ldg(x0 + (size_t)j9 * VEC + lane);

    float4 s0, s1;
    s0.x = c * (a0.x + a1.x + a2.x + a3.x + a4.x);
    s0.y = c * (a0.y + a1.y + a2.y + a3.y + a4.y);
    s0.z = c * (a0.z + a1.z + a2.z + a3.z + a4.z);
    s0.w = c * (a0.w + a1.w + a2.w + a3.w + a4.w);
    s1.x = c * (b0.x + b1.x + b2.x + b3.x + b4.x);
    s1.y = c * (b0.y + b1.y + b2.y + b3.y + b4.y);
    s1.z = c * (b0.z + b1.z + b2.z + b3.z + b4.z);
    s1.w = c * (b0.w + b1.w + b2.w + b3.w + b4.w);

    __half2 h00 = __floats2half2_rn(s0.x, s0.y);
    __half2 h01 = __floats2half2_rn(s0.z, s0.w);
    __half2 h10 = __floats2half2_rn(s1.x, s1.y);
    __half2 h11 = __floats2half2_rn(s1.z, s1.w);
    uint2 u0, u1;
    u0.x = *reinterpret_cast<unsigned int*>(&h00);
    u0.y = *reinterpret_cast<unsigned int*>(&h01);
    u1.x = *reinterpret_cast<unsigned int*>(&h10);
    u1.y = *reinterpret_cast<unsigned int*>(&h11);
    g_x1h[(size_t)row0 * VEC + lane] = u0;
    g_x1h[(size_t)(row0 + 1) * VEC + lane] = u1;
}

// Kernel 2: out[n] = x0[n] + x1[n] + c * sum_k x1[idx[n,k]], 2 rows/warp.
// EXACT R10 body (23.14 us measured, best layer2 ever): x1h reads via
// evict_last policy (protect the 25.6 MB), out via write-through (no L2 alloc).
__global__ __launch_bounds__(THREADS) void spmm_layer2(
    const float4* __restrict__ x0,
    const int*    __restrict__ idx,
    float4*       __restrict__ out,
    float c)
{
    int warp = blockIdx.x * WARPS_PER_BLOCK + (threadIdx.x >> 5);
    int lane = threadIdx.x & 31;
    int row0 = warp * 2;
    unsigned long long pol = mk_evict_last_policy();

    int my = 0;
    if (lane < 2 * KNN_K) my = __ldg(idx + row0 * KNN_K + lane);
    int j0 = __shfl_sync(0xffffffffu, my, 0);
    int j1 = __shfl_sync(0xffffffffu, my, 1);
    int j2 = __shfl_sync(0xffffffffu, my, 2);
    int j3 = __shfl_sync(0xffffffffu, my, 3);
    int j4 = __shfl_sync(0xffffffffu, my, 4);
    int j5 = __shfl_sync(0xffffffffu, my, 5);
    int j6 = __shfl_sync(0xffffffffu, my, 6);
    int j7 = __shfl_sync(0xffffffffu, my, 7);
    int j8 = __shfl_sync(0xffffffffu, my, 8);
    int j9 = __shfl_sync(0xffffffffu, my, 9);

    const uint2* x1h = g_x1h;

    uint2 g0 = ldg_keep_u2(x1h + (size_t)j0 * VEC + lane, pol);
    uint2 g1 = ldg_keep_u2(x1h + (size_t)j1 * VEC + lane, pol);
    uint2 g2 = ldg_keep_u2(x1h + (size_t)j2 * VEC + lane, pol);
    uint2 g3 = ldg_keep_u2(x1h + (size_t)j3 * VEC + lane, pol);
    uint2 g4 = ldg_keep_u2(x1h + (size_t)j4 * VEC + lane, pol);
    uint2 h0 = ldg_keep_u2(x1h + (size_t)j5 * VEC + lane, pol);
    uint2 h1 = ldg_keep_u2(x1h + (size_t)j6 * VEC + lane, pol);
    uint2 h2 = ldg_keep_u2(x1h + (size_t)j7 * VEC + lane, pol);
    uint2 h3 = ldg_keep_u2(x1h + (size_t)j8 * VEC + lane, pol);
    uint2 h4 = ldg_keep_u2(x1h + (size_t)j9 * VEC + lane, pol);
    uint2 gr0 = ldg_keep_u2(x1h + (size_t)row0 * VEC + lane, pol);
    uint2 gr1 = ldg_keep_u2(x1h + (size_t)(row0 + 1) * VEC + lane, pol);
    // x0 residual rows: streaming (evict-first), zero L2 footprint.
    float4 r00 = __ldcs(x0 + (size_t)row0 * VEC + lane);
    float4 r01 = __ldcs(x0 + (size_t)(row0 + 1) * VEC + lane);

    // Row 0 compute.
    float2 A0 = __half22float2(*reinterpret_cast<__half2*>(&g0.x));
    float2 A1 = __half22float2(*reinterpret_cast<__half2*>(&g0.y));
    float2 B0 = __half22float2(*reinterpret_cast<__half2*>(&g1.x));
    float2 B1 = __half22float2(*reinterpret_cast<__half2*>(&g1.y));
    float2 C0 = __half22float2(*reinterpret_cast<__half2*>(&g2.x));
    float2 C1 = __half22float2(*reinterpret_cast<__half2*>(&g2.y));
    float2 D0 = __half22float2(*reinterpret_cast<__half2*>(&g3.x));
    float2 D1 = __half22float2(*reinterpret_cast<__half2*>(&g3.y));
    float2 E0 = __half22float2(*reinterpret_cast<__half2*>(&g4.x));
    float2 E1 = __half22float2(*reinterpret_cast<__half2*>(&g4.y));
    float2 R0 = __half22float2(*reinterpret_cast<__half2*>(&gr0.x));
    float2 R1 = __half22float2(*reinterpret_cast<__half2*>(&gr0.y));

    float4 s0;
    s0.x = r00.x + R0.x + c * (A0.x + B0.x + C0.x + D0.x + E0.x);
    s0.y = r00.y + R0.y + c * (A0.y + B0.y + C0.y + D0.y + E0.y);
    s0.z = r00.z + R1.x + c * (A1.x + B1.x + C1.x + D1.x + E1.x);
    s0.w = r00.w + R1.y + c * (A1.y + B1.y + C1.y + D1.y + E1.y);
    __stwt(out + (size_t)row0 * VEC + lane, s0);   // write-through, no L2 alloc

    // Row 1 compute.
    A0 = __half22float2(*reinterpret_cast<__half2*>(&h0.x));
    A1 = __half22float2(*reinterpret_cast<__half2*>(&h0.y));
    B0 = __half22float2(*reinterpret_cast<__half2*>(&h1.x));
    B1 = __half22float2(*reinterpret_cast<__half2*>(&h1.y));
    C0 = __half22float2(*reinterpret_cast<__half2*>(&h2.x));
    C1 = __half22float2(*reinterpret_cast<__half2*>(&h2.y));
    D0 = __half22float2(*reinterpret_cast<__half2*>(&h3.x));
    D1 = __half22float2(*reinterpret_cast<__half2*>(&h3.y));
    E0 = __half22float2(*reinterpret_cast<__half2*>(&h4.x));
    E1 = __half22float2(*reinterpret_cast<__half2*>(&h4.y));
    R0 = __half22float2(*reinterpret_cast<__half2*>(&gr1.x));
    R1 = __half22float2(*reinterpret_cast<__half2*>(&gr1.y));

    float4 s1;
    s1.x = r01.x + R0.x + c * (A0.x + B0.x + C0.x + D0.x + E0.x);
    s1.y = r01.y + R0.y + c * (A0.y + B0.y + C0.y + D0.y + E0.y);
    s1.z = r01.z + R1.x + c * (A1.x + B1.x + C1.x + D1.x + E1.x);
    s1.w = r01.w + R1.y + c * (A1.y + B1.y + C1.y + D1.y + E1.y);
    __stwt(out + (size_t)(row0 + 1) * VEC + lane, s1);
}

extern "C" void kernel_launch(void* const* d_in, const int* in_sizes, int n_in,
                              void* d_out, int out_size)
{
    const float4* x0  = (const float4*)d_in[0];   // item_rep [N, 128] f32
    const int*    idx = (const int*)d_in[1];      // knn_ind  [N, 5] i32
    float4*       out = (float4*)d_out;

    // vals[n,k] = (K+1e-7)^-0.5 * (K+1e-7)^-0.5 == 1/(K+1e-7): a constant.
    float c = (float)(1.0 / (5.0 + 1e-7));

    spmm_layer1<<<BLOCKS, THREADS>>>(x0, idx, c);
    spmm_layer2<<<BLOCKS, THREADS>>>(x0, idx, out, c);
}

// round 17
// speedup vs baseline: 1.6612x; 1.0189x over previous
#include <cuda_runtime.h>
#include <cuda_fp16.h>

#define N_ITEMS 100000
#define KNN_K   5
#define VEC     32                 // 32 float4 (or uint2) per 128-elem row
#define WARPS_PER_BLOCK 8
#define THREADS (WARPS_PER_BLOCK * 32)
// 2 rows per warp, no tail: 100000 / 2 = 50000 warps = 6250 blocks exactly.
#define BLOCKS  (N_ITEMS / 2 / WARPS_PER_BLOCK)

// Intermediate layer-1 output in fp16 (25.6 MB): halves layer2's gather bytes.
// Hot read set = x0 (51.2) + x1h (25.6) = 76.8 MB < 126 MB L2. The out store
// is write-through (the ONLY delta vs the verified-best R6 kernel) so the
// 51 MB output stream never allocates in L2 and the hot set can survive
// across kernels and graph replays.
__device__ uint2 g_x1h[(size_t)N_ITEMS * VEC];

// Kernel 1: x1h[n] = fp16( c * sum_k x0[idx[n,k]] ), 2 rows/warp.
// EXACT R6 body (best measured layer1: 15.9 us).
__global__ __launch_bounds__(THREADS) void spmm_layer1(
    const float4* __restrict__ x0,
    const int*    __restrict__ idx,
    float c)
{
    int warp = blockIdx.x * WARPS_PER_BLOCK + (threadIdx.x >> 5);
    int lane = threadIdx.x & 31;
    int row0 = warp * 2;

    // One lane-parallel load covers both rows' 10 indices; shfl distributes.
    int my = 0;
    if (lane < 2 * KNN_K) my = __ldg(idx + row0 * KNN_K + lane);
    int j0 = __shfl_sync(0xffffffffu, my, 0);
    int j1 = __shfl_sync(0xffffffffu, my, 1);
    int j2 = __shfl_sync(0xffffffffu, my, 2);
    int j3 = __shfl_sync(0xffffffffu, my, 3);
    int j4 = __shfl_sync(0xffffffffu, my, 4);
    int j5 = __shfl_sync(0xffffffffu, my, 5);
    int j6 = __shfl_sync(0xffffffffu, my, 6);
    int j7 = __shfl_sync(0xffffffffu, my, 7);
    int j8 = __shfl_sync(0xffffffffu, my, 8);
    int j9 = __shfl_sync(0xffffffffu, my, 9);

    float4 a0 = __ldg(x0 + (size_t)j0 * VEC + lane);
    float4 a1 = __ldg(x0 + (size_t)j1 * VEC + lane);
    float4 a2 = __ldg(x0 + (size_t)j2 * VEC + lane);
    float4 a3 = __ldg(x0 + (size_t)j3 * VEC + lane);
    float4 a4 = __ldg(x0 + (size_t)j4 * VEC + lane);
    float4 b0 = __ldg(x0 + (size_t)j5 * VEC + lane);
    float4 b1 = __ldg(x0 + (size_t)j6 * VEC + lane);
    float4 b2 = __ldg(x0 + (size_t)j7 * VEC + lane);
    float4 b3 = __ldg(x0 + (size_t)j8 * VEC + lane);
    float4 b4 = __ldg(x0 + (size_t)j9 * VEC + lane);

    float4 s0, s1;
    s0.x = c * (a0.x + a1.x + a2.x + a3.x + a4.x);
    s0.y = c * (a0.y + a1.y + a2.y + a3.y + a4.y);
    s0.z = c * (a0.z + a1.z + a2.z + a3.z + a4.z);
    s0.w = c * (a0.w + a1.w + a2.w + a3.w + a4.w);
    s1.x = c * (b0.x + b1.x + b2.x + b3.x + b4.x);
    s1.y = c * (b0.y + b1.y + b2.y + b3.y + b4.y);
    s1.z = c * (b0.z + b1.z + b2.z + b3.z + b4.z);
    s1.w = c * (b0.w + b1.w + b2.w + b3.w + b4.w);

    __half2 h00 = __floats2half2_rn(s0.x, s0.y);
    __half2 h01 = __floats2half2_rn(s0.z, s0.w);
    __half2 h10 = __floats2half2_rn(s1.x, s1.y);
    __half2 h11 = __floats2half2_rn(s1.z, s1.w);
    uint2 u0, u1;
    u0.x = *reinterpret_cast<unsigned int*>(&h00);
    u0.y = *reinterpret_cast<unsigned int*>(&h01);
    u1.x = *reinterpret_cast<unsigned int*>(&h10);
    u1.y = *reinterpret_cast<unsigned int*>(&h11);
    g_x1h[(size_t)row0 * VEC + lane] = u0;
    g_x1h[(size_t)(row0 + 1) * VEC + lane] = u1;
}

// Kernel 2: out[n] = x0[n] + x1[n] + c * sum_k x1[idx[n,k]], 2 rows/warp.
// EXACT R6 body with ONE change: out stored via __stwt (write-through) so the
// output stream never allocates in L2. All reads are plain __ldg — R16 proved
// __ldcs on the x0 rows demotes x0 and slows the next replay's layer1.
__global__ __launch_bounds__(THREADS) void spmm_layer2(
    const float4* __restrict__ x0,
    const int*    __restrict__ idx,
    float4*       __restrict__ out,
    float c)
{
    int warp = blockIdx.x * WARPS_PER_BLOCK + (threadIdx.x >> 5);
    int lane = threadIdx.x & 31;
    int row0 = warp * 2;

    int my = 0;
    if (lane < 2 * KNN_K) my = __ldg(idx + row0 * KNN_K + lane);
    int j0 = __shfl_sync(0xffffffffu, my, 0);
    int j1 = __shfl_sync(0xffffffffu, my, 1);
    int j2 = __shfl_sync(0xffffffffu, my, 2);
    int j3 = __shfl_sync(0xffffffffu, my, 3);
    int j4 = __shfl_sync(0xffffffffu, my, 4);
    int j5 = __shfl_sync(0xffffffffu, my, 5);
    int j6 = __shfl_sync(0xffffffffu, my, 6);
    int j7 = __shfl_sync(0xffffffffu, my, 7);
    int j8 = __shfl_sync(0xffffffffu, my, 8);
    int j9 = __shfl_sync(0xffffffffu, my, 9);

    const uint2* x1h = g_x1h;

    uint2 g0 = __ldg(x1h + (size_t)j0 * VEC + lane);
    uint2 g1 = __ldg(x1h + (size_t)j1 * VEC + lane);
    uint2 g2 = __ldg(x1h + (size_t)j2 * VEC + lane);
    uint2 g3 = __ldg(x1h + (size_t)j3 * VEC + lane);
    uint2 g4 = __ldg(x1h + (size_t)j4 * VEC + lane);
    uint2 h0 = __ldg(x1h + (size_t)j5 * VEC + lane);
    uint2 h1 = __ldg(x1h + (size_t)j6 * VEC + lane);
    uint2 h2 = __ldg(x1h + (size_t)j7 * VEC + lane);
    uint2 h3 = __ldg(x1h + (size_t)j8 * VEC + lane);
    uint2 h4 = __ldg(x1h + (size_t)j9 * VEC + lane);
    uint2 gr0 = __ldg(x1h + (size_t)row0 * VEC + lane);
    uint2 gr1 = __ldg(x1h + (size_t)(row0 + 1) * VEC + lane);
    float4 r00 = __ldg(x0 + (size_t)row0 * VEC + lane);        // keep x0's L2
    float4 r01 = __ldg(x0 + (size_t)(row0 + 1) * VEC + lane);  // state intact

    // Row 0 compute.
    float2 A0 = __half22float2(*reinterpret_cast<__half2*>(&g0.x));
    float2 A1 = __half22float2(*reinterpret_cast<__half2*>(&g0.y));
    float2 B0 = __half22float2(*reinterpret_cast<__half2*>(&g1.x));
    float2 B1 = __half22float2(*reinterpret_cast<__half2*>(&g1.y));
    float2 C0 = __half22float2(*reinterpret_cast<__half2*>(&g2.x));
    float2 C1 = __half22float2(*reinterpret_cast<__half2*>(&g2.y));
    float2 D0 = __half22float2(*reinterpret_cast<__half2*>(&g3.x));
    float2 D1 = __half22float2(*reinterpret_cast<__half2*>(&g3.y));
    float2 E0 = __half22float2(*reinterpret_cast<__half2*>(&g4.x));
    float2 E1 = __half22float2(*reinterpret_cast<__half2*>(&g4.y));
    float2 R0 = __half22float2(*reinterpret_cast<__half2*>(&gr0.x));
    float2 R1 = __half22float2(*reinterpret_cast<__half2*>(&gr0.y));

    float4 s0;
    s0.x = r00.x + R0.x + c * (A0.x + B0.x + C0.x + D0.x + E0.x);
    s0.y = r00.y + R0.y + c * (A0.y + B0.y + C0.y + D0.y + E0.y);
    s0.z = r00.z + R1.x + c * (A1.x + B1.x + C1.x + D1.x + E1.x);
    s0.w = r00.w + R1.y + c * (A1.y + B1.y + C1.y + D1.y + E1.y);
    __stwt(out + (size_t)row0 * VEC + lane, s0);   // write-through: no L2 alloc

    // Row 1 compute.
    A0 = __half22float2(*reinterpret_cast<__half2*>(&h0.x));
    A1 = __half22float2(*reinterpret_cast<__half2*>(&h0.y));
    B0 = __half22float2(*reinterpret_cast<__half2*>(&h1.x));
    B1 = __half22float2(*reinterpret_cast<__half2*>(&h1.y));
    C0 = __half22float2(*reinterpret_cast<__half2*>(&h2.x));
    C1 = __half22float2(*reinterpret_cast<__half2*>(&h2.y));
    D0 = __half22float2(*reinterpret_cast<__half2*>(&h3.x));
    D1 = __half22float2(*reinterpret_cast<__half2*>(&h3.y));
    E0 = __half22float2(*reinterpret_cast<__half2*>(&h4.x));
    E1 = __half22float2(*reinterpret_cast<__half2*>(&h4.y));
    R0 = __half22float2(*reinterpret_cast<__half2*>(&gr1.x));
    R1 = __half22float2(*reinterpret_cast<__half2*>(&gr1.y));

    float4 s1;
    s1.x = r01.x + R0.x + c * (A0.x + B0.x + C0.x + D0.x + E0.x);
    s1.y = r01.y + R0.y + c * (A0.y + B0.y + C0.y + D0.y + E0.y);
    s1.z = r01.z + R1.x + c * (A1.x + B1.x + C1.x + D1.x + E1.x);
    s1.w = r01.w + R1.y + c * (A1.y + B1.y + C1.y + D1.y + E1.y);
    __stwt(out + (size_t)(row0 + 1) * VEC + lane, s1);
}

extern "C" void kernel_launch(void* const* d_in, const int* in_sizes, int n_in,
                              void* d_out, int out_size)
{
    const float4* x0  = (const float4*)d_in[0];   // item_rep [N, 128] f32
    const int*    idx = (const int*)d_in[1];      // knn_ind  [N, 5] i32
    float4*       out = (float4*)d_out;

    // vals[n,k] = (K+1e-7)^-0.5 * (K+1e-7)^-0.5 == 1/(K+1e-7): a constant.
    float c = (float)(1.0 / (5.0 + 1e-7));

    spmm_layer1<<<BLOCKS, THREADS>>>(x0, idx, c);
    spmm_layer2<<<BLOCKS, THREADS>>>(x0, idx, out, c);
}